// round 10
// baseline (speedup 1.0000x reference)
#include <cuda_runtime.h>
#include <cuda_bf16.h>

#define B_TOT   65536
#define TST     40
#define DT      0.1f
#define MCH     64        // batch rows per CTA
#define NTHR    256       // 8 warps = 2 m-groups x 4 n-groups
#define NPADN   416       // 4 gate blocks x 104 padded units
#define KEL     104       // padded K elems (102 real), 13 chunks of 16B
#define ROWB    208       // operand-image row stride (odd chunk count -> ldsm conflict-free)

// ---- SMEM byte offsets (112 KB total -> 2 CTAs/SM) ----
#define OFF_R    0                 // 416*208 = 86528
#define OFF_A0   86528             // 64*208  = 13312
#define OFF_A1   99840             // 13312
#define OFF_ATT  113152            // 4*64*4  = 1024
#define OFF_AW   114176            // 100*4   = 400
#define SMEM_BYTES 114576

// ---- static device scratch ----
__device__ __align__(16) float         g_xk[(size_t)B_TOT * 400];  // permuted col=4u+g, fp32
__device__ __align__(16) float         g_c [(size_t)B_TOT * 100];  // LSTM cell state (L2-resident)
__device__ __align__(16) __nv_bfloat16 g_Rimg[NPADN * KEL];        // B image [n=104g+u][k]

// j-tile assignment per n-group (13 j-tiles over 4 groups)
__device__ __constant__ int JBASE[4] = {0, 4, 7, 10};
__device__ __constant__ int JCNT[4]  = {4, 3, 3, 3};

// ============================ helpers ============================
__device__ __forceinline__ unsigned smem_u32(const void* p) {
    unsigned a;
    asm("{ .reg .u64 t; cvta.to.shared.u64 t, %1; cvt.u32.u64 %0, t; }" : "=r"(a) : "l"(p));
    return a;
}
__device__ __forceinline__ float fast_ex2(float x){ float y; asm("ex2.approx.f32 %0,%1;" : "=f"(y) : "f"(x)); return y; }
__device__ __forceinline__ float fast_rcp(float x){ float y; asm("rcp.approx.f32 %0,%1;" : "=f"(y) : "f"(x)); return y; }
__device__ __forceinline__ float fsigm(float x){ return fast_rcp(1.f + fast_ex2(-1.4426950408889634f * x)); }
__device__ __forceinline__ float htanh(float x){ float y; asm("tanh.approx.f32 %0,%1;" : "=f"(y) : "f"(x)); return y; }
__device__ __forceinline__ float tsigm(float x){ return fmaf(0.5f, htanh(0.5f * x), 0.5f); }

__device__ __forceinline__ void ldsm_x4(unsigned* r, unsigned addr) {
    asm volatile("ldmatrix.sync.aligned.m8n8.x4.shared.b16 {%0,%1,%2,%3}, [%4];"
        : "=r"(r[0]), "=r"(r[1]), "=r"(r[2]), "=r"(r[3]) : "r"(addr));
}
__device__ __forceinline__ void ldsm_x2(unsigned& r0, unsigned& r1, unsigned addr) {
    asm volatile("ldmatrix.sync.aligned.m8n8.x2.shared.b16 {%0,%1}, [%2];"
        : "=r"(r0), "=r"(r1) : "r"(addr));
}
__device__ __forceinline__ void ldsm_x1(unsigned& r0, unsigned addr) {
    asm volatile("ldmatrix.sync.aligned.m8n8.x1.shared.b16 {%0}, [%1];"
        : "=r"(r0) : "r"(addr));
}
__device__ __forceinline__ void mma16(float* c, const unsigned* a, unsigned b0, unsigned b1) {
    asm volatile("mma.sync.aligned.m16n8k16.row.col.f32.bf16.bf16.f32 "
        "{%0,%1,%2,%3}, {%4,%5,%6,%7}, {%8,%9}, {%0,%1,%2,%3};"
        : "+f"(c[0]), "+f"(c[1]), "+f"(c[2]), "+f"(c[3])
        : "r"(a[0]), "r"(a[1]), "r"(a[2]), "r"(a[3]), "r"(b0), "r"(b1));
}
__device__ __forceinline__ void mma8(float* c, unsigned a0, unsigned a1, unsigned b0) {
    asm volatile("mma.sync.aligned.m16n8k8.row.col.f32.bf16.bf16.f32 "
        "{%0,%1,%2,%3}, {%4,%5}, {%6}, {%0,%1,%2,%3};"
        : "+f"(c[0]), "+f"(c[1]), "+f"(c[2]), "+f"(c[3])
        : "r"(a0), "r"(a1), "r"(b0));
}

// ============================ setup: B image + proj + xk(fp32) ============================
__global__ void __launch_bounds__(256) setup_kernel(
    const float* __restrict__ z, const float* __restrict__ W1, const float* __restrict__ b1,
    const float* __restrict__ W2, const float* __restrict__ b2,
    const float* __restrict__ lstm_k, const float* __restrict__ lstm_r,
    const float* __restrict__ lstm_b)
{
    if (blockIdx.x >= 1024) {
        int i = (blockIdx.x - 1024) * 256 + threadIdx.x;
        if (i < NPADN * KEL) {
            int n = i / KEL, k = i % KEL;
            int g = n / 104, u = n % 104;
            float v = 0.f;
            if (u < 100) {
                int col = u + 100 * g;
                if (k < 100)      v = lstm_r[(size_t)k * 400 + col];
                else if (k < 102) v = lstm_k[(size_t)(50 + (k - 100)) * 400 + col];
            }
            g_Rimg[i] = __float2bfloat16_rn(v);
        }
        return;
    }
    const int warp = threadIdx.x >> 5, lane = threadIdx.x & 31;
    for (int b = blockIdx.x * 8 + warp; b < B_TOT; b += 8192) {
        float zr[4];
        #pragma unroll
        for (int q = 0; q < 4; q++) zr[q] = z[(size_t)b * 128 + q * 32 + lane];

        float a0 = b1[lane];
        float a1 = (lane < 18) ? b1[32 + lane] : 0.f;
        for (int i = 0; i < 128; i++) {
            float zi = __shfl_sync(0xffffffffu, zr[i >> 5], i & 31);
            a0 = fmaf(zi, W1[i * 50 + lane], a0);
            if (lane < 18) a1 = fmaf(zi, W1[i * 50 + 32 + lane], a1);
        }
        float p10 = fmaxf(a0, 0.f), p11 = fmaxf(a1, 0.f);

        float c0 = b2[lane];
        float c1 = (lane < 18) ? b2[32 + lane] : 0.f;
        for (int i = 0; i < 50; i++) {
            float pi = __shfl_sync(0xffffffffu, (i < 32) ? p10 : p11, i & 31);
            c0 = fmaf(pi, W2[i * 50 + lane], c0);
            if (lane < 18) c1 = fmaf(pi, W2[i * 50 + 32 + lane], c1);
        }
        float p20 = fmaxf(c0, 0.f), p21 = fmaxf(c1, 0.f);

        float acc[13];
        #pragma unroll
        for (int q = 0; q < 13; q++) { int j = lane + 32 * q; acc[q] = (j < 400) ? lstm_b[j] : 0.f; }
        for (int i = 0; i < 50; i++) {
            float pi = __shfl_sync(0xffffffffu, (i < 32) ? p20 : p21, i & 31);
            const float* kr = lstm_k + (size_t)i * 400;
            #pragma unroll
            for (int q = 0; q < 13; q++) { int j = lane + 32 * q; if (j < 400) acc[q] = fmaf(pi, kr[j], acc[q]); }
        }
        float* xo = g_xk + (size_t)b * 400;
        #pragma unroll
        for (int q = 0; q < 13; q++) {
            int j = lane + 32 * q;
            if (j < 400) xo[4 * (j % 100) + (j / 100)] = acc[q];
        }
    }
}

// ============================ rollout ============================
__global__ void __launch_bounds__(NTHR, 2) rollout_kernel(
    const float* __restrict__ idm_params, const float* __restrict__ idm_s,
    const float* __restrict__ sdv_acts,   const float* __restrict__ att_w,
    const float* __restrict__ att_b,      float* __restrict__ out)
{
    extern __shared__ char sm[];
    const unsigned sbase = smem_u32(sm);
    float* att_f = (float*)(sm + OFF_ATT);
    float* aw_f  = (float*)(sm + OFF_AW);

    const int tid = threadIdx.x, lane = tid & 31, wid = tid >> 5;
    const int b0 = blockIdx.x * MCH;

    // ---- init: R image, zero A bufs, aw ----
    {
        const uint4* src = (const uint4*)g_Rimg;
        uint4* dR = (uint4*)(sm + OFF_R);
        for (int i = tid; i < 86528 / 16; i += NTHR) dR[i] = src[i];
        uint4 zz = make_uint4(0, 0, 0, 0);
        uint4* dA = (uint4*)(sm + OFF_A0);
        for (int i = tid; i < 26624 / 16; i += NTHR) dA[i] = zz;
        for (int i = tid; i < 100; i += NTHR) aw_f[i] = att_w[i];
    }
    __syncthreads();
    if (tid < MCH) {   // sdv(0) into A0 at k=100,101
        const float2 sd = *(const float2*)(sdv_acts + (size_t)(b0 + tid) * TST * 2);
        __nv_bfloat162 pk = __floats2bfloat162_rn(sd.x, sd.y);
        *(unsigned*)(sm + OFF_A0 + tid * ROWB + 200) = *(unsigned*)&pk;
    }

    // ---- roles: 8 warps; wid = 2*ng + mg ----
    const int mg = wid & 1, ng = wid >> 1;
    const int jbase = JBASE[ng], jcnt = JCNT[ng];
    const int rbase = 32 * mg;
    const int amat = lane >> 3;
    const int cg = lane >> 2, ct = lane & 3;
    const int bnr = lane & 7, bq = lane >> 3;

    float ego_v = 0.f, ego_x = 0.f;
    if (tid < MCH) {
        const float* s0p = idm_s + (size_t)(b0 + tid) * TST * 12;
        ego_v = s0p[0]; ego_x = s0p[3];
    }
    __syncthreads();

    for (int t = 0; t < TST; t++) {
        const unsigned acur = (t & 1) ? OFF_A1 : OFF_A0;
        const unsigned anxt = (t & 1) ? OFF_A0 : OFF_A1;

        // ---- A fragments for BOTH m-tiles (joint-mt: B read once per j,g) ----
        unsigned afr[2][6][4], a8[2][2];
        #pragma unroll
        for (int mt = 0; mt < 2; mt++) {
            const int arow = rbase + 16 * mt + (lane & 7) + ((amat & 1) << 3);
            const int akoff = amat >> 1;
            #pragma unroll
            for (int s = 0; s < 6; s++)
                ldsm_x4(afr[mt][s], sbase + acur + (unsigned)arow * ROWB + (unsigned)((2 * s + akoff) << 4));
            const int a8r = rbase + 16 * mt + (lane & 7) + (((lane >> 3) & 1) << 3);
            ldsm_x2(a8[mt][0], a8[mt][1], sbase + acur + (unsigned)a8r * ROWB + 192u);
        }

        float attp[2][2] = {{0.f, 0.f}, {0.f, 0.f}};

        #pragma unroll
        for (int jl = 0; jl < 4; jl++) {
            if (jl < jcnt) {
                const int j = jbase + jl;
                float C[2][4][4];
                #pragma unroll
                for (int mt = 0; mt < 2; mt++)
                    #pragma unroll
                    for (int g = 0; g < 4; g++)
                        #pragma unroll
                        for (int q = 0; q < 4; q++) C[mt][g][q] = 0.f;

                #pragma unroll
                for (int g = 0; g < 4; g++) {
                    const int n = 104 * g + 8 * j + bnr;
                    const unsigned baddr = sbase + OFF_R + (unsigned)n * ROWB;
                    unsigned b4[4], bb;
                    ldsm_x4(b4, baddr + ((0 + bq) << 4));
                    mma16(C[0][g], afr[0][0], b4[0], b4[1]);
                    mma16(C[1][g], afr[1][0], b4[0], b4[1]);
                    mma16(C[0][g], afr[0][1], b4[2], b4[3]);
                    mma16(C[1][g], afr[1][1], b4[2], b4[3]);
                    ldsm_x4(b4, baddr + ((4 + bq) << 4));
                    mma16(C[0][g], afr[0][2], b4[0], b4[1]);
                    mma16(C[1][g], afr[1][2], b4[0], b4[1]);
                    mma16(C[0][g], afr[0][3], b4[2], b4[3]);
                    mma16(C[1][g], afr[1][3], b4[2], b4[3]);
                    ldsm_x4(b4, baddr + ((8 + bq) << 4));
                    mma16(C[0][g], afr[0][4], b4[0], b4[1]);
                    mma16(C[1][g], afr[1][4], b4[0], b4[1]);
                    mma16(C[0][g], afr[0][5], b4[2], b4[3]);
                    mma16(C[1][g], afr[1][5], b4[2], b4[3]);
                    ldsm_x1(bb, baddr + 192u);
                    mma8(C[0][g], a8[0][0], a8[0][1], bb);
                    mma8(C[1][g], a8[1][0], a8[1][1], bb);
                }

                // ---- epilogue: gates in-thread; xk + c via L2 ----
                const int u0 = 8 * j + 2 * ct;
                if (u0 < 100) {
                    const float aw0 = aw_f[u0], aw1 = aw_f[u0 + 1];
                    #pragma unroll
                    for (int mt = 0; mt < 2; mt++) {
                        #pragma unroll
                        for (int ph = 0; ph < 2; ph++) {
                            const int row = rbase + 16 * mt + cg + 8 * ph;
                            const float4* xp = (const float4*)(g_xk + (size_t)(b0 + row) * 400 + 4 * u0);
                            const float4 xv0 = __ldg(xp);
                            const float4 xv1 = __ldg(xp + 1);
                            float2* cp = (float2*)(g_c + (size_t)(b0 + row) * 100 + u0);
                            float2 cold = (t > 0) ? *cp : make_float2(0.f, 0.f);

                            float z0 = C[mt][0][2 * ph] + xv0.x;
                            float z1 = C[mt][1][2 * ph] + xv0.y;
                            float z2 = C[mt][2][2 * ph] + xv0.z;
                            float z3 = C[mt][3][2 * ph] + xv0.w;
                            float cn0 = fsigm(z1) * cold.x + tsigm(z0) * htanh(z2);
                            float h0 = htanh(cn0) * tsigm(z3);

                            float y0 = C[mt][0][2 * ph + 1] + xv1.x;
                            float y1 = C[mt][1][2 * ph + 1] + xv1.y;
                            float y2 = C[mt][2][2 * ph + 1] + xv1.z;
                            float y3 = C[mt][3][2 * ph + 1] + xv1.w;
                            float cn1 = fsigm(y1) * cold.y + tsigm(y0) * htanh(y2);
                            float h1 = htanh(cn1) * tsigm(y3);

                            *cp = make_float2(cn0, cn1);
                            attp[mt][ph] = fmaf(h0, aw0, fmaf(h1, aw1, attp[mt][ph]));
                            __nv_bfloat162 pk = __floats2bfloat162_rn(h0, h1);
                            *(unsigned*)(sm + anxt + row * ROWB + u0 * 2) = *(unsigned*)&pk;
                        }
                    }
                }
            }
        }

        // ---- att partial reduce over ct, write to smem ----
        #pragma unroll
        for (int mt = 0; mt < 2; mt++)
            #pragma unroll
            for (int ph = 0; ph < 2; ph++) {
                float v = attp[mt][ph];
                v += __shfl_xor_sync(0xffffffffu, v, 1);
                v += __shfl_xor_sync(0xffffffffu, v, 2);
                if (ct == 0) att_f[ng * 64 + rbase + 16 * mt + cg + 8 * ph] = v;
            }
        __syncthreads();

        // ---- IDM + integrate + store (threads 0..63) ----
        if (tid < MCH) {
            const int b = b0 + tid;
            const float* pp = idm_params + b * 5;
            const float vdes = pp[0], tgap = pp[1], jamx = pp[2], amax = pp[3];
            const float gden = 2.f * sqrtf(amax * pp[4]);
            const float* srow = idm_s + ((size_t)b * TST + t) * 12;
            float fv = srow[1], mv = srow[2], fx = srow[4], mx = srow[5];
            float fex = srow[10], mex = srow[11];

            float s = att_f[tid] + att_f[64 + tid] + att_f[128 + tid] + att_f[192 + tid];
            float att = fsigm(s + att_b[0]);
            att = (fex * att + (1.f - fex)) * mex;

            float v = ego_v, x = ego_x;
            float dx1 = fminf(fmaxf(fx - x, 0.1f), 1000.f);
            float gap1 = tgap * v + v * (v - fv) / gden;
            float dg1 = jamx + fmaxf(gap1, 0.f);
            float r1 = v / vdes; float r1s = r1 * r1;
            float r2 = dg1 / dx1;
            float ef = amax * (1.f - r1s * r1s - r2 * r2);
            ef = fminf(fmaxf(ef, -100000.f), 100000.f);

            float dx2 = fminf(fmaxf(mx - x, 0.1f), 1000.f);
            float gap2 = tgap * v + v * (v - mv) / gden;
            float dg2 = jamx + fmaxf(gap2, 0.f);
            float r3 = dg2 / dx2;
            float em2 = amax * (1.f - r1s * r1s - r3 * r3);
            em2 = fminf(fmaxf(em2, -100000.f), 100000.f);

            float act = (1.f - att) * ef + att * em2;
            float vn = v + act * DT;
            ego_x = x + vn * DT + 0.5f * act * DT * DT;
            ego_v = vn;

            out[(size_t)b * TST + t] = act;
            out[(size_t)B_TOT * TST + (size_t)b * TST + t] = att;

            if (t + 1 < TST) {   // stage sdv(t+1) into next A buffer
                const float2 sd = *(const float2*)(sdv_acts + ((size_t)b * TST + t + 1) * 2);
                __nv_bfloat162 pk = __floats2bfloat162_rn(sd.x, sd.y);
                *(unsigned*)(sm + anxt + tid * ROWB + 200) = *(unsigned*)&pk;
            }
        }
        __syncthreads();
    }
}

// ============================ launch ============================
extern "C" void kernel_launch(void* const* d_in, const int* in_sizes, int n_in,
                              void* d_out, int out_size) {
    const float* sampled_z  = (const float*)d_in[0];
    const float* idm_params = (const float*)d_in[1];
    const float* idm_s      = (const float*)d_in[2];
    const float* sdv_acts   = (const float*)d_in[3];
    const float* W1         = (const float*)d_in[4];
    const float* b1         = (const float*)d_in[5];
    const float* W2         = (const float*)d_in[6];
    const float* b2         = (const float*)d_in[7];
    const float* lstm_k     = (const float*)d_in[8];
    const float* lstm_r     = (const float*)d_in[9];
    const float* lstm_b     = (const float*)d_in[10];
    const float* att_w      = (const float*)d_in[11];
    const float* att_b      = (const float*)d_in[12];
    float* out = (float*)d_out;

    cudaFuncSetAttribute(rollout_kernel, cudaFuncAttributeMaxDynamicSharedMemorySize, SMEM_BYTES);

    setup_kernel<<<1024 + (NPADN * KEL + 255) / 256, 256>>>(
        sampled_z, W1, b1, W2, b2, lstm_k, lstm_r, lstm_b);
    rollout_kernel<<<B_TOT / MCH, NTHR, SMEM_BYTES>>>(idm_params, idm_s, sdv_acts, att_w, att_b, out);
}

// round 11
// speedup vs baseline: 1.2543x; 1.2543x over previous
#include <cuda_runtime.h>
#include <cuda_bf16.h>

#define B_TOT   65536
#define TST     40
#define DT      0.1f
#define MCH     64        // batch rows per CTA
#define NTHR    384       // 12 warps = 2 m-groups x 6 n-groups
#define NPADN   416       // 4 gate blocks x 104 padded units
#define KEL     104       // padded K elems (102 real), 13 chunks of 16B
#define ROWB    208       // operand-image row stride (odd chunk count -> ldsm conflict-free)
#define XKW     404       // xk smem row stride in floats (1616 B)

// ---- SMEM byte offsets (1 CTA/SM, 218.5 KB) ----
#define OFF_R    0                 // 416*208 = 86528
#define OFF_A0   86528             // 64*208  = 13312
#define OFF_A1   99840             // 13312
#define OFF_XK   113152            // 64*1616 = 103424
#define OFF_ATT  216576            // 6*64*4  = 1536
#define OFF_AW   218112            // 100*4   = 400
#define SMEM_BYTES 218512

// ---- static device scratch ----
__device__ __align__(16) float         g_xk[(size_t)B_TOT * 400];  // permuted col=4u+g, fp32
__device__ __align__(16) __nv_bfloat16 g_Rimg[NPADN * KEL];        // B image [n=104g+u][k]

// j-tile assignment per n-group (13 j-tiles over 6 groups; SMSP load 7/7/6/6)
__device__ __constant__ int JBASE[6] = {0, 3, 5, 7, 9, 11};
__device__ __constant__ int JCNT[6]  = {3, 2, 2, 2, 2, 2};

// ============================ helpers ============================
__device__ __forceinline__ unsigned smem_u32(const void* p) {
    unsigned a;
    asm("{ .reg .u64 t; cvta.to.shared.u64 t, %1; cvt.u32.u64 %0, t; }" : "=r"(a) : "l"(p));
    return a;
}
__device__ __forceinline__ float fast_ex2(float x){ float y; asm("ex2.approx.f32 %0,%1;" : "=f"(y) : "f"(x)); return y; }
__device__ __forceinline__ float fast_rcp(float x){ float y; asm("rcp.approx.f32 %0,%1;" : "=f"(y) : "f"(x)); return y; }
__device__ __forceinline__ float fsigm(float x){ return fast_rcp(1.f + fast_ex2(-1.4426950408889634f * x)); }
__device__ __forceinline__ float htanh(float x){ float y; asm("tanh.approx.f32 %0,%1;" : "=f"(y) : "f"(x)); return y; }
__device__ __forceinline__ float tsigm(float x){ return fmaf(0.5f, htanh(0.5f * x), 0.5f); }

__device__ __forceinline__ void ldsm_x4(unsigned* r, unsigned addr) {
    asm volatile("ldmatrix.sync.aligned.m8n8.x4.shared.b16 {%0,%1,%2,%3}, [%4];"
        : "=r"(r[0]), "=r"(r[1]), "=r"(r[2]), "=r"(r[3]) : "r"(addr));
}
__device__ __forceinline__ void ldsm_x2(unsigned& r0, unsigned& r1, unsigned addr) {
    asm volatile("ldmatrix.sync.aligned.m8n8.x2.shared.b16 {%0,%1}, [%2];"
        : "=r"(r0), "=r"(r1) : "r"(addr));
}
__device__ __forceinline__ void ldsm_x1(unsigned& r0, unsigned addr) {
    asm volatile("ldmatrix.sync.aligned.m8n8.x1.shared.b16 {%0}, [%1];"
        : "=r"(r0) : "r"(addr));
}
__device__ __forceinline__ void mma16(float* c, const unsigned* a, unsigned b0, unsigned b1) {
    asm volatile("mma.sync.aligned.m16n8k16.row.col.f32.bf16.bf16.f32 "
        "{%0,%1,%2,%3}, {%4,%5,%6,%7}, {%8,%9}, {%0,%1,%2,%3};"
        : "+f"(c[0]), "+f"(c[1]), "+f"(c[2]), "+f"(c[3])
        : "r"(a[0]), "r"(a[1]), "r"(a[2]), "r"(a[3]), "r"(b0), "r"(b1));
}
__device__ __forceinline__ void mma8(float* c, unsigned a0, unsigned a1, unsigned b0) {
    asm volatile("mma.sync.aligned.m16n8k8.row.col.f32.bf16.bf16.f32 "
        "{%0,%1,%2,%3}, {%4,%5}, {%6}, {%0,%1,%2,%3};"
        : "+f"(c[0]), "+f"(c[1]), "+f"(c[2]), "+f"(c[3])
        : "r"(a0), "r"(a1), "r"(b0));
}

// ============================ setup: B image + proj + xk(fp32) ============================
__global__ void __launch_bounds__(256) setup_kernel(
    const float* __restrict__ z, const float* __restrict__ W1, const float* __restrict__ b1,
    const float* __restrict__ W2, const float* __restrict__ b2,
    const float* __restrict__ lstm_k, const float* __restrict__ lstm_r,
    const float* __restrict__ lstm_b)
{
    if (blockIdx.x >= 1024) {
        int i = (blockIdx.x - 1024) * 256 + threadIdx.x;
        if (i < NPADN * KEL) {
            int n = i / KEL, k = i % KEL;
            int g = n / 104, u = n % 104;
            float v = 0.f;
            if (u < 100) {
                int col = u + 100 * g;
                if (k < 100)      v = lstm_r[(size_t)k * 400 + col];
                else if (k < 102) v = lstm_k[(size_t)(50 + (k - 100)) * 400 + col];
            }
            g_Rimg[i] = __float2bfloat16_rn(v);
        }
        return;
    }
    const int warp = threadIdx.x >> 5, lane = threadIdx.x & 31;
    for (int b = blockIdx.x * 8 + warp; b < B_TOT; b += 8192) {
        float zr[4];
        #pragma unroll
        for (int q = 0; q < 4; q++) zr[q] = z[(size_t)b * 128 + q * 32 + lane];

        float a0 = b1[lane];
        float a1 = (lane < 18) ? b1[32 + lane] : 0.f;
        for (int i = 0; i < 128; i++) {
            float zi = __shfl_sync(0xffffffffu, zr[i >> 5], i & 31);
            a0 = fmaf(zi, W1[i * 50 + lane], a0);
            if (lane < 18) a1 = fmaf(zi, W1[i * 50 + 32 + lane], a1);
        }
        float p10 = fmaxf(a0, 0.f), p11 = fmaxf(a1, 0.f);

        float c0 = b2[lane];
        float c1 = (lane < 18) ? b2[32 + lane] : 0.f;
        for (int i = 0; i < 50; i++) {
            float pi = __shfl_sync(0xffffffffu, (i < 32) ? p10 : p11, i & 31);
            c0 = fmaf(pi, W2[i * 50 + lane], c0);
            if (lane < 18) c1 = fmaf(pi, W2[i * 50 + 32 + lane], c1);
        }
        float p20 = fmaxf(c0, 0.f), p21 = fmaxf(c1, 0.f);

        float acc[13];
        #pragma unroll
        for (int q = 0; q < 13; q++) { int j = lane + 32 * q; acc[q] = (j < 400) ? lstm_b[j] : 0.f; }
        for (int i = 0; i < 50; i++) {
            float pi = __shfl_sync(0xffffffffu, (i < 32) ? p20 : p21, i & 31);
            const float* kr = lstm_k + (size_t)i * 400;
            #pragma unroll
            for (int q = 0; q < 13; q++) { int j = lane + 32 * q; if (j < 400) acc[q] = fmaf(pi, kr[j], acc[q]); }
        }
        float* xo = g_xk + (size_t)b * 400;
        #pragma unroll
        for (int q = 0; q < 13; q++) {
            int j = lane + 32 * q;
            if (j < 400) xo[4 * (j % 100) + (j / 100)] = acc[q];
        }
    }
}

// ============================ rollout ============================
__global__ void __launch_bounds__(NTHR, 1) rollout_kernel(
    const float* __restrict__ idm_params, const float* __restrict__ idm_s,
    const float* __restrict__ sdv_acts,   const float* __restrict__ att_w,
    const float* __restrict__ att_b,      float* __restrict__ out)
{
    extern __shared__ char sm[];
    const unsigned sbase = smem_u32(sm);
    float* xk_f  = (float*)(sm + OFF_XK);
    float* att_f = (float*)(sm + OFF_ATT);
    float* aw_f  = (float*)(sm + OFF_AW);

    const int tid = threadIdx.x, lane = tid & 31, wid = tid >> 5;
    const int b0 = blockIdx.x * MCH;

    // ---- init: R image, zero A bufs, xk fp32, aw ----
    {
        const uint4* src = (const uint4*)g_Rimg;
        uint4* dR = (uint4*)(sm + OFF_R);
        for (int i = tid; i < 86528 / 16; i += NTHR) dR[i] = src[i];
        uint4 zz = make_uint4(0, 0, 0, 0);
        uint4* dA = (uint4*)(sm + OFF_A0);
        for (int i = tid; i < 26624 / 16; i += NTHR) dA[i] = zz;
        for (int i = tid; i < 100; i += NTHR) aw_f[i] = att_w[i];
        for (int idx = tid; idx < 64 * 400; idx += NTHR) {
            int row = idx / 400, jj = idx % 400;
            xk_f[row * XKW + jj] = g_xk[(size_t)(b0 + row) * 400 + jj];
        }
    }
    __syncthreads();
    if (tid < MCH) {   // sdv(0) into A0 at k=100,101
        const float2 sd = *(const float2*)(sdv_acts + (size_t)(b0 + tid) * TST * 2);
        __nv_bfloat162 pk = __floats2bfloat162_rn(sd.x, sd.y);
        *(unsigned*)(sm + OFF_A0 + tid * ROWB + 200) = *(unsigned*)&pk;
    }

    // ---- roles: 12 warps; mg = wid&1, ng = wid>>1 ----
    const int mg = wid & 1, ng = wid >> 1;
    const int jbase = JBASE[ng], jcnt = JCNT[ng];
    const int rbase = 32 * mg;
    const int amat = lane >> 3;
    const int cg = lane >> 2, ct = lane & 3;
    const int bnr = lane & 7, bq = lane >> 3;

    float c_st[2][3][4];
    #pragma unroll
    for (int a = 0; a < 2; a++)
        #pragma unroll
        for (int b = 0; b < 3; b++)
            #pragma unroll
            for (int c = 0; c < 4; c++) c_st[a][b][c] = 0.f;

    float ego_v = 0.f, ego_x = 0.f;
    if (tid < MCH) {
        const float* s0p = idm_s + (size_t)(b0 + tid) * TST * 12;
        ego_v = s0p[0]; ego_x = s0p[3];
    }
    __syncthreads();

    for (int t = 0; t < TST; t++) {
        const unsigned acur = (t & 1) ? OFF_A1 : OFF_A0;
        const unsigned anxt = (t & 1) ? OFF_A0 : OFF_A1;

        // ---- A fragments for BOTH m-tiles (joint-mt: B read once per j,g) ----
        unsigned afr[2][6][4], a8[2][2];
        #pragma unroll
        for (int mt = 0; mt < 2; mt++) {
            const int arow = rbase + 16 * mt + (lane & 7) + ((amat & 1) << 3);
            const int akoff = amat >> 1;
            #pragma unroll
            for (int s = 0; s < 6; s++)
                ldsm_x4(afr[mt][s], sbase + acur + (unsigned)arow * ROWB + (unsigned)((2 * s + akoff) << 4));
            const int a8r = rbase + 16 * mt + (lane & 7) + (((lane >> 3) & 1) << 3);
            ldsm_x2(a8[mt][0], a8[mt][1], sbase + acur + (unsigned)a8r * ROWB + 192u);
        }

        float attp[2][2] = {{0.f, 0.f}, {0.f, 0.f}};

        #pragma unroll
        for (int jl = 0; jl < 3; jl++) {
            if (jl < jcnt) {
                const int j = jbase + jl;
                float C[2][4][4];
                #pragma unroll
                for (int mt = 0; mt < 2; mt++)
                    #pragma unroll
                    for (int g = 0; g < 4; g++)
                        #pragma unroll
                        for (int q = 0; q < 4; q++) C[mt][g][q] = 0.f;

                #pragma unroll
                for (int g = 0; g < 4; g++) {
                    const int n = 104 * g + 8 * j + bnr;
                    const unsigned baddr = sbase + OFF_R + (unsigned)n * ROWB;
                    unsigned b4[4], bb;
                    ldsm_x4(b4, baddr + ((0 + bq) << 4));
                    mma16(C[0][g], afr[0][0], b4[0], b4[1]);
                    mma16(C[1][g], afr[1][0], b4[0], b4[1]);
                    mma16(C[0][g], afr[0][1], b4[2], b4[3]);
                    mma16(C[1][g], afr[1][1], b4[2], b4[3]);
                    ldsm_x4(b4, baddr + ((4 + bq) << 4));
                    mma16(C[0][g], afr[0][2], b4[0], b4[1]);
                    mma16(C[1][g], afr[1][2], b4[0], b4[1]);
                    mma16(C[0][g], afr[0][3], b4[2], b4[3]);
                    mma16(C[1][g], afr[1][3], b4[2], b4[3]);
                    ldsm_x4(b4, baddr + ((8 + bq) << 4));
                    mma16(C[0][g], afr[0][4], b4[0], b4[1]);
                    mma16(C[1][g], afr[1][4], b4[0], b4[1]);
                    mma16(C[0][g], afr[0][5], b4[2], b4[3]);
                    mma16(C[1][g], afr[1][5], b4[2], b4[3]);
                    ldsm_x1(bb, baddr + 192u);
                    mma8(C[0][g], a8[0][0], a8[0][1], bb);
                    mma8(C[1][g], a8[1][0], a8[1][1], bb);
                }

                // ---- epilogue: gates in-thread; xk from SMEM; c in regs ----
                const int u0 = 8 * j + 2 * ct;
                if (u0 < 100) {
                    const float aw0 = aw_f[u0], aw1 = aw_f[u0 + 1];
                    #pragma unroll
                    for (int mt = 0; mt < 2; mt++) {
                        #pragma unroll
                        for (int ph = 0; ph < 2; ph++) {
                            const int row = rbase + 16 * mt + cg + 8 * ph;
                            const float* xr = xk_f + row * XKW + 4 * u0;
                            const float4 xv0 = *(const float4*)(xr);
                            const float4 xv1 = *(const float4*)(xr + 4);
                            float z0 = C[mt][0][2 * ph] + xv0.x;
                            float z1 = C[mt][1][2 * ph] + xv0.y;
                            float z2 = C[mt][2][2 * ph] + xv0.z;
                            float z3 = C[mt][3][2 * ph] + xv0.w;
                            float cn0 = fsigm(z1) * c_st[mt][jl][2 * ph] + tsigm(z0) * htanh(z2);
                            c_st[mt][jl][2 * ph] = cn0;
                            float h0 = htanh(cn0) * tsigm(z3);

                            float y0 = C[mt][0][2 * ph + 1] + xv1.x;
                            float y1 = C[mt][1][2 * ph + 1] + xv1.y;
                            float y2 = C[mt][2][2 * ph + 1] + xv1.z;
                            float y3 = C[mt][3][2 * ph + 1] + xv1.w;
                            float cn1 = fsigm(y1) * c_st[mt][jl][2 * ph + 1] + tsigm(y0) * htanh(y2);
                            c_st[mt][jl][2 * ph + 1] = cn1;
                            float h1 = htanh(cn1) * tsigm(y3);

                            attp[mt][ph] = fmaf(h0, aw0, fmaf(h1, aw1, attp[mt][ph]));
                            __nv_bfloat162 pk = __floats2bfloat162_rn(h0, h1);
                            *(unsigned*)(sm + anxt + row * ROWB + u0 * 2) = *(unsigned*)&pk;
                        }
                    }
                }
            }
        }

        // ---- att partial reduce over ct, write to smem ----
        #pragma unroll
        for (int mt = 0; mt < 2; mt++)
            #pragma unroll
            for (int ph = 0; ph < 2; ph++) {
                float v = attp[mt][ph];
                v += __shfl_xor_sync(0xffffffffu, v, 1);
                v += __shfl_xor_sync(0xffffffffu, v, 2);
                if (ct == 0) att_f[ng * 64 + rbase + 16 * mt + cg + 8 * ph] = v;
            }
        __syncthreads();

        // ---- IDM + integrate + store (threads 0..63) ----
        if (tid < MCH) {
            const int b = b0 + tid;
            const float* pp = idm_params + b * 5;
            const float vdes = pp[0], tgap = pp[1], jamx = pp[2], amax = pp[3];
            const float gden = 2.f * sqrtf(amax * pp[4]);
            const float* srow = idm_s + ((size_t)b * TST + t) * 12;
            float fv = srow[1], mv = srow[2], fx = srow[4], mx = srow[5];
            float fex = srow[10], mex = srow[11];

            float s = 0.f;
            #pragma unroll
            for (int q = 0; q < 6; q++) s += att_f[q * 64 + tid];
            float att = fsigm(s + att_b[0]);
            att = (fex * att + (1.f - fex)) * mex;

            float v = ego_v, x = ego_x;
            float dx1 = fminf(fmaxf(fx - x, 0.1f), 1000.f);
            float gap1 = tgap * v + v * (v - fv) / gden;
            float dg1 = jamx + fmaxf(gap1, 0.f);
            float r1 = v / vdes; float r1s = r1 * r1;
            float r2 = dg1 / dx1;
            float ef = amax * (1.f - r1s * r1s - r2 * r2);
            ef = fminf(fmaxf(ef, -100000.f), 100000.f);

            float dx2 = fminf(fmaxf(mx - x, 0.1f), 1000.f);
            float gap2 = tgap * v + v * (v - mv) / gden;
            float dg2 = jamx + fmaxf(gap2, 0.f);
            float r3 = dg2 / dx2;
            float em2 = amax * (1.f - r1s * r1s - r3 * r3);
            em2 = fminf(fmaxf(em2, -100000.f), 100000.f);

            float act = (1.f - att) * ef + att * em2;
            float vn = v + act * DT;
            ego_x = x + vn * DT + 0.5f * act * DT * DT;
            ego_v = vn;

            out[(size_t)b * TST + t] = act;
            out[(size_t)B_TOT * TST + (size_t)b * TST + t] = att;

            if (t + 1 < TST) {   // stage sdv(t+1) into next A buffer
                const float2 sd = *(const float2*)(sdv_acts + ((size_t)b * TST + t + 1) * 2);
                __nv_bfloat162 pk = __floats2bfloat162_rn(sd.x, sd.y);
                *(unsigned*)(sm + anxt + tid * ROWB + 200) = *(unsigned*)&pk;
            }
        }
        __syncthreads();
    }
}

// ============================ launch ============================
extern "C" void kernel_launch(void* const* d_in, const int* in_sizes, int n_in,
                              void* d_out, int out_size) {
    const float* sampled_z  = (const float*)d_in[0];
    const float* idm_params = (const float*)d_in[1];
    const float* idm_s      = (const float*)d_in[2];
    const float* sdv_acts   = (const float*)d_in[3];
    const float* W1         = (const float*)d_in[4];
    const float* b1         = (const float*)d_in[5];
    const float* W2         = (const float*)d_in[6];
    const float* b2         = (const float*)d_in[7];
    const float* lstm_k     = (const float*)d_in[8];
    const float* lstm_r     = (const float*)d_in[9];
    const float* lstm_b     = (const float*)d_in[10];
    const float* att_w      = (const float*)d_in[11];
    const float* att_b      = (const float*)d_in[12];
    float* out = (float*)d_out;

    cudaFuncSetAttribute(rollout_kernel, cudaFuncAttributeMaxDynamicSharedMemorySize, SMEM_BYTES);

    setup_kernel<<<1024 + (NPADN * KEL + 255) / 256, 256>>>(
        sampled_z, W1, b1, W2, b2, lstm_k, lstm_r, lstm_b);
    rollout_kernel<<<B_TOT / MCH, NTHR, SMEM_BYTES>>>(idm_params, idm_s, sdv_acts, att_w, att_b, out);
}

// round 12
// speedup vs baseline: 1.4146x; 1.1278x over previous
#include <cuda_runtime.h>
#include <cuda_bf16.h>

#define B_TOT   65536
#define TST     40
#define DT      0.1f
#define MCH     64        // batch rows per CTA
#define NTHR    256       // 8 warps = 2 m-groups x 4 n-groups
#define NPADN   416       // 4 gate blocks x 104 padded units
#define KEL     104       // padded K elems (102 real), 13 chunks of 16B
#define ROWB    208       // operand-image row stride (odd chunk count -> ldsm conflict-free)

// ---- SMEM byte offsets (112.9 KB -> 2 CTAs/SM) ----
#define OFF_R    0                 // 416*208 = 86528
#define OFF_A0   86528             // 64*208  = 13312
#define OFF_A1   99840             // 13312
#define OFF_ATT  113152            // 2 buf * 4*64*4 = 2048
#define OFF_AW   115200            // 100*4 = 400
#define SMEM_BYTES 115600

// ---- static device scratch ----
__device__ __align__(16) float         g_xk[(size_t)B_TOT * 400];  // permuted col=4u+g, fp32
__device__ __align__(16) __nv_bfloat16 g_Rimg[NPADN * KEL];        // B image [n=104g+u][k]

// j-tile assignment per n-group (13 j-tiles over 4 groups)
__device__ __constant__ int JBASE[4] = {0, 4, 7, 10};
__device__ __constant__ int JCNT[4]  = {4, 3, 3, 3};

// ============================ helpers ============================
__device__ __forceinline__ unsigned smem_u32(const void* p) {
    unsigned a;
    asm("{ .reg .u64 t; cvta.to.shared.u64 t, %1; cvt.u32.u64 %0, t; }" : "=r"(a) : "l"(p));
    return a;
}
__device__ __forceinline__ float fast_ex2(float x){ float y; asm("ex2.approx.f32 %0,%1;" : "=f"(y) : "f"(x)); return y; }
__device__ __forceinline__ float fast_rcp(float x){ float y; asm("rcp.approx.f32 %0,%1;" : "=f"(y) : "f"(x)); return y; }
__device__ __forceinline__ float fsigm(float x){ return fast_rcp(1.f + fast_ex2(-1.4426950408889634f * x)); }
__device__ __forceinline__ float htanh(float x){ float y; asm("tanh.approx.f32 %0,%1;" : "=f"(y) : "f"(x)); return y; }
__device__ __forceinline__ float tsigm(float x){ return fmaf(0.5f, htanh(0.5f * x), 0.5f); }

__device__ __forceinline__ void ldsm_x4(unsigned* r, unsigned addr) {
    asm volatile("ldmatrix.sync.aligned.m8n8.x4.shared.b16 {%0,%1,%2,%3}, [%4];"
        : "=r"(r[0]), "=r"(r[1]), "=r"(r[2]), "=r"(r[3]) : "r"(addr));
}
__device__ __forceinline__ void ldsm_x2(unsigned& r0, unsigned& r1, unsigned addr) {
    asm volatile("ldmatrix.sync.aligned.m8n8.x2.shared.b16 {%0,%1}, [%2];"
        : "=r"(r0), "=r"(r1) : "r"(addr));
}
__device__ __forceinline__ void ldsm_x1(unsigned& r0, unsigned addr) {
    asm volatile("ldmatrix.sync.aligned.m8n8.x1.shared.b16 {%0}, [%1];"
        : "=r"(r0) : "r"(addr));
}
__device__ __forceinline__ void mma16(float* c, const unsigned* a, unsigned b0, unsigned b1) {
    asm volatile("mma.sync.aligned.m16n8k16.row.col.f32.bf16.bf16.f32 "
        "{%0,%1,%2,%3}, {%4,%5,%6,%7}, {%8,%9}, {%0,%1,%2,%3};"
        : "+f"(c[0]), "+f"(c[1]), "+f"(c[2]), "+f"(c[3])
        : "r"(a[0]), "r"(a[1]), "r"(a[2]), "r"(a[3]), "r"(b0), "r"(b1));
}
__device__ __forceinline__ void mma8(float* c, unsigned a0, unsigned a1, unsigned b0) {
    asm volatile("mma.sync.aligned.m16n8k8.row.col.f32.bf16.bf16.f32 "
        "{%0,%1,%2,%3}, {%4,%5}, {%6}, {%0,%1,%2,%3};"
        : "+f"(c[0]), "+f"(c[1]), "+f"(c[2]), "+f"(c[3])
        : "r"(a0), "r"(a1), "r"(b0));
}

// ============================ setup: B image + proj + xk(fp32) ============================
__global__ void __launch_bounds__(256) setup_kernel(
    const float* __restrict__ z, const float* __restrict__ W1, const float* __restrict__ b1,
    const float* __restrict__ W2, const float* __restrict__ b2,
    const float* __restrict__ lstm_k, const float* __restrict__ lstm_r,
    const float* __restrict__ lstm_b)
{
    if (blockIdx.x >= 1024) {
        int i = (blockIdx.x - 1024) * 256 + threadIdx.x;
        if (i < NPADN * KEL) {
            int n = i / KEL, k = i % KEL;
            int g = n / 104, u = n % 104;
            float v = 0.f;
            if (u < 100) {
                int col = u + 100 * g;
                if (k < 100)      v = lstm_r[(size_t)k * 400 + col];
                else if (k < 102) v = lstm_k[(size_t)(50 + (k - 100)) * 400 + col];
            }
            g_Rimg[i] = __float2bfloat16_rn(v);
        }
        return;
    }
    const int warp = threadIdx.x >> 5, lane = threadIdx.x & 31;
    for (int b = blockIdx.x * 8 + warp; b < B_TOT; b += 8192) {
        float zr[4];
        #pragma unroll
        for (int q = 0; q < 4; q++) zr[q] = z[(size_t)b * 128 + q * 32 + lane];

        float a0 = b1[lane];
        float a1 = (lane < 18) ? b1[32 + lane] : 0.f;
        for (int i = 0; i < 128; i++) {
            float zi = __shfl_sync(0xffffffffu, zr[i >> 5], i & 31);
            a0 = fmaf(zi, W1[i * 50 + lane], a0);
            if (lane < 18) a1 = fmaf(zi, W1[i * 50 + 32 + lane], a1);
        }
        float p10 = fmaxf(a0, 0.f), p11 = fmaxf(a1, 0.f);

        float c0 = b2[lane];
        float c1 = (lane < 18) ? b2[32 + lane] : 0.f;
        for (int i = 0; i < 50; i++) {
            float pi = __shfl_sync(0xffffffffu, (i < 32) ? p10 : p11, i & 31);
            c0 = fmaf(pi, W2[i * 50 + lane], c0);
            if (lane < 18) c1 = fmaf(pi, W2[i * 50 + 32 + lane], c1);
        }
        float p20 = fmaxf(c0, 0.f), p21 = fmaxf(c1, 0.f);

        float acc[13];
        #pragma unroll
        for (int q = 0; q < 13; q++) { int j = lane + 32 * q; acc[q] = (j < 400) ? lstm_b[j] : 0.f; }
        for (int i = 0; i < 50; i++) {
            float pi = __shfl_sync(0xffffffffu, (i < 32) ? p20 : p21, i & 31);
            const float* kr = lstm_k + (size_t)i * 400;
            #pragma unroll
            for (int q = 0; q < 13; q++) { int j = lane + 32 * q; if (j < 400) acc[q] = fmaf(pi, kr[j], acc[q]); }
        }
        float* xo = g_xk + (size_t)b * 400;
        #pragma unroll
        for (int q = 0; q < 13; q++) {
            int j = lane + 32 * q;
            if (j < 400) xo[4 * (j % 100) + (j / 100)] = acc[q];
        }
    }
}

// ============================ rollout ============================
__global__ void __launch_bounds__(NTHR, 2) rollout_kernel(
    const float* __restrict__ idm_params, const float* __restrict__ idm_s,
    const float* __restrict__ sdv_acts,   const float* __restrict__ att_w,
    const float* __restrict__ att_b,      float* __restrict__ out)
{
    extern __shared__ char sm[];
    const unsigned sbase = smem_u32(sm);
    float* att_f = (float*)(sm + OFF_ATT);
    float* aw_f  = (float*)(sm + OFF_AW);

    const int tid = threadIdx.x, lane = tid & 31, wid = tid >> 5;
    const int b0 = blockIdx.x * MCH;

    // ---- init: R image, zero A bufs, aw ----
    {
        const uint4* src = (const uint4*)g_Rimg;
        uint4* dR = (uint4*)(sm + OFF_R);
        for (int i = tid; i < 86528 / 16; i += NTHR) dR[i] = src[i];
        uint4 zz = make_uint4(0, 0, 0, 0);
        uint4* dA = (uint4*)(sm + OFF_A0);
        for (int i = tid; i < 26624 / 16; i += NTHR) dA[i] = zz;
        for (int i = tid; i < 100; i += NTHR) aw_f[i] = att_w[i];
    }
    __syncthreads();
    if (tid < MCH) {   // sdv(0) into A0 at k=100,101
        const float2 sd = *(const float2*)(sdv_acts + (size_t)(b0 + tid) * TST * 2);
        __nv_bfloat162 pk = __floats2bfloat162_rn(sd.x, sd.y);
        *(unsigned*)(sm + OFF_A0 + tid * ROWB + 200) = *(unsigned*)&pk;
    }

    // ---- roles: 8 warps; mg = wid&1, ng = wid>>1 ----
    const int mg = wid & 1, ng = wid >> 1;
    const int jbase = JBASE[ng], jcnt = JCNT[ng];
    const int rbase = 32 * mg;
    const int amat = lane >> 3;
    const int cg = lane >> 2, ct = lane & 3;
    const int bnr = lane & 7, bq = lane >> 3;

    float c_st[2][4][4];
    #pragma unroll
    for (int a = 0; a < 2; a++)
        #pragma unroll
        for (int b = 0; b < 4; b++)
            #pragma unroll
            for (int c = 0; c < 4; c++) c_st[a][b][c] = 0.f;

    float ego_v = 0.f, ego_x = 0.f;
    if (tid < MCH) {
        const float* s0p = idm_s + (size_t)(b0 + tid) * TST * 12;
        ego_v = s0p[0]; ego_x = s0p[3];
    }
    __syncthreads();

    for (int t = 0; t < TST; t++) {
        const unsigned acur = (t & 1) ? OFF_A1 : OFF_A0;
        const unsigned anxt = (t & 1) ? OFF_A0 : OFF_A1;
        float* atb = att_f + (t & 1) * 256;

        // stage sdv(t+1) into anxt NOW (its last reads ended before sync(t-1))
        if (tid < MCH && t + 1 < TST) {
            const float2 sd = *(const float2*)(sdv_acts + ((size_t)(b0 + tid) * TST + t + 1) * 2);
            __nv_bfloat162 pk = __floats2bfloat162_rn(sd.x, sd.y);
            *(unsigned*)(sm + anxt + tid * ROWB + 200) = *(unsigned*)&pk;
        }

        float attp[2][2] = {{0.f, 0.f}, {0.f, 0.f}};

        #pragma unroll
        for (int mt = 0; mt < 2; mt++) {
            // ---- A fragments for this 16-row m-tile ----
            unsigned afr[6][4], a80, a81;
            {
                const int arow = rbase + 16 * mt + (lane & 7) + ((amat & 1) << 3);
                const int akoff = amat >> 1;
                #pragma unroll
                for (int s = 0; s < 6; s++)
                    ldsm_x4(afr[s], sbase + acur + (unsigned)arow * ROWB + (unsigned)((2 * s + akoff) << 4));
                const int a8r = rbase + 16 * mt + (lane & 7) + (((lane >> 3) & 1) << 3);
                ldsm_x2(a80, a81, sbase + acur + (unsigned)a8r * ROWB + 192u);
            }

            #pragma unroll
            for (int jl = 0; jl < 4; jl++) {
                if (jl < jcnt) {
                    const int j = jbase + jl;
                    unsigned baddr[4];
                    #pragma unroll
                    for (int g = 0; g < 4; g++)
                        baddr[g] = sbase + OFF_R + (unsigned)(104 * g + 8 * j + bnr) * ROWB;

                    float C[4][4];
                    #pragma unroll
                    for (int g = 0; g < 4; g++)
                        #pragma unroll
                        for (int q = 0; q < 4; q++) C[g][q] = 0.f;

                    // g-interleaved MMA: 4 independent accumulation chains
                    #pragma unroll
                    for (int s2 = 0; s2 < 3; s2++) {
                        unsigned b4[4][4];
                        #pragma unroll
                        for (int g = 0; g < 4; g++)
                            ldsm_x4(b4[g], baddr[g] + (unsigned)((4 * s2 + bq) << 4));
                        #pragma unroll
                        for (int g = 0; g < 4; g++)
                            mma16(C[g], afr[2 * s2], b4[g][0], b4[g][1]);
                        #pragma unroll
                        for (int g = 0; g < 4; g++)
                            mma16(C[g], afr[2 * s2 + 1], b4[g][2], b4[g][3]);
                    }
                    #pragma unroll
                    for (int g = 0; g < 4; g++) {
                        unsigned bb;
                        ldsm_x1(bb, baddr[g] + 192u);
                        mma8(C[g], a80, a81, bb);
                    }

                    // ---- epilogue: gates in-thread; xk via L2; c in regs ----
                    const int u0 = 8 * j + 2 * ct;
                    if (u0 < 100) {
                        const float aw0 = aw_f[u0], aw1 = aw_f[u0 + 1];
                        #pragma unroll
                        for (int ph = 0; ph < 2; ph++) {
                            const int row = rbase + 16 * mt + cg + 8 * ph;
                            const float4* xp = (const float4*)(g_xk + (size_t)(b0 + row) * 400 + 4 * u0);
                            const float4 xv0 = __ldg(xp);
                            const float4 xv1 = __ldg(xp + 1);
                            float z0 = C[0][2 * ph] + xv0.x;
                            float z1 = C[1][2 * ph] + xv0.y;
                            float z2 = C[2][2 * ph] + xv0.z;
                            float z3 = C[3][2 * ph] + xv0.w;
                            float cn0 = fsigm(z1) * c_st[mt][jl][2 * ph] + tsigm(z0) * htanh(z2);
                            c_st[mt][jl][2 * ph] = cn0;
                            float h0 = htanh(cn0) * tsigm(z3);

                            float y0 = C[0][2 * ph + 1] + xv1.x;
                            float y1 = C[1][2 * ph + 1] + xv1.y;
                            float y2 = C[2][2 * ph + 1] + xv1.z;
                            float y3 = C[3][2 * ph + 1] + xv1.w;
                            float cn1 = fsigm(y1) * c_st[mt][jl][2 * ph + 1] + tsigm(y0) * htanh(y2);
                            c_st[mt][jl][2 * ph + 1] = cn1;
                            float h1 = htanh(cn1) * tsigm(y3);

                            attp[mt][ph] = fmaf(h0, aw0, fmaf(h1, aw1, attp[mt][ph]));
                            __nv_bfloat162 pk = __floats2bfloat162_rn(h0, h1);
                            *(unsigned*)(sm + anxt + row * ROWB + u0 * 2) = *(unsigned*)&pk;
                        }
                    }
                }
            }
        }

        // ---- att partial reduce over ct, write to this step's buffer ----
        #pragma unroll
        for (int mt = 0; mt < 2; mt++)
            #pragma unroll
            for (int ph = 0; ph < 2; ph++) {
                float v = attp[mt][ph];
                v += __shfl_xor_sync(0xffffffffu, v, 1);
                v += __shfl_xor_sync(0xffffffffu, v, 2);
                if (ct == 0) atb[ng * 64 + rbase + 16 * mt + cg + 8 * ph] = v;
            }
        __syncthreads();   // the ONLY barrier per step

        // ---- IDM + integrate + store (threads 0..63); others proceed to t+1 ----
        if (tid < MCH) {
            const int b = b0 + tid;
            const float* pp = idm_params + b * 5;
            const float vdes = pp[0], tgap = pp[1], jamx = pp[2], amax = pp[3];
            const float gden = 2.f * sqrtf(amax * pp[4]);
            const float* srow = idm_s + ((size_t)b * TST + t) * 12;
            float fv = srow[1], mv = srow[2], fx = srow[4], mx = srow[5];
            float fex = srow[10], mex = srow[11];

            float s = atb[tid] + atb[64 + tid] + atb[128 + tid] + atb[192 + tid];
            float att = fsigm(s + att_b[0]);
            att = (fex * att + (1.f - fex)) * mex;

            float v = ego_v, x = ego_x;
            float dx1 = fminf(fmaxf(fx - x, 0.1f), 1000.f);
            float gap1 = tgap * v + v * (v - fv) / gden;
            float dg1 = jamx + fmaxf(gap1, 0.f);
            float r1 = v / vdes; float r1s = r1 * r1;
            float r2 = dg1 / dx1;
            float ef = amax * (1.f - r1s * r1s - r2 * r2);
            ef = fminf(fmaxf(ef, -100000.f), 100000.f);

            float dx2 = fminf(fmaxf(mx - x, 0.1f), 1000.f);
            float gap2 = tgap * v + v * (v - mv) / gden;
            float dg2 = jamx + fmaxf(gap2, 0.f);
            float r3 = dg2 / dx2;
            float em2 = amax * (1.f - r1s * r1s - r3 * r3);
            em2 = fminf(fmaxf(em2, -100000.f), 100000.f);

            float act = (1.f - att) * ef + att * em2;
            float vn = v + act * DT;
            ego_x = x + vn * DT + 0.5f * act * DT * DT;
            ego_v = vn;

            out[(size_t)b * TST + t] = act;
            out[(size_t)B_TOT * TST + (size_t)b * TST + t] = att;
        }
    }
}

// ============================ launch ============================
extern "C" void kernel_launch(void* const* d_in, const int* in_sizes, int n_in,
                              void* d_out, int out_size) {
    const float* sampled_z  = (const float*)d_in[0];
    const float* idm_params = (const float*)d_in[1];
    const float* idm_s      = (const float*)d_in[2];
    const float* sdv_acts   = (const float*)d_in[3];
    const float* W1         = (const float*)d_in[4];
    const float* b1         = (const float*)d_in[5];
    const float* W2         = (const float*)d_in[6];
    const float* b2         = (const float*)d_in[7];
    const float* lstm_k     = (const float*)d_in[8];
    const float* lstm_r     = (const float*)d_in[9];
    const float* lstm_b     = (const float*)d_in[10];
    const float* att_w      = (const float*)d_in[11];
    const float* att_b      = (const float*)d_in[12];
    float* out = (float*)d_out;

    cudaFuncSetAttribute(rollout_kernel, cudaFuncAttributeMaxDynamicSharedMemorySize, SMEM_BYTES);

    setup_kernel<<<1024 + (NPADN * KEL + 255) / 256, 256>>>(
        sampled_z, W1, b1, W2, b2, lstm_k, lstm_r, lstm_b);
    rollout_kernel<<<B_TOT / MCH, NTHR, SMEM_BYTES>>>(idm_params, idm_s, sdv_acts, att_w, att_b, out);
}

// round 13
// speedup vs baseline: 1.4899x; 1.0532x over previous
#include <cuda_runtime.h>
#include <cuda_bf16.h>

#define B_TOT   65536
#define TST     40
#define DT      0.1f
#define MCH     64        // batch rows per CTA
#define NTHR    512       // 16 warps = 2 m-groups x 8 n-groups
#define NPADN   416       // 4 gate blocks x 104 padded units
#define KEL     104       // padded K elems (102 real), 13 chunks of 16B
#define ROWB    208       // operand-image row stride (odd chunk count -> ldsm conflict-free)
#define XKW     404       // xk smem row stride in floats (1616 B)

// ---- SMEM byte offsets (1 CTA/SM, ~216 KB) ----
#define OFF_R    0                 // 416*208 = 86528
#define OFF_A0   86528             // 64*208  = 13312
#define OFF_A1   99840             // 13312
#define OFF_XK   113152            // 64*1616 = 103424
#define OFF_ATT  216576            // 2 buf * 8*64*4 = 4096
#define OFF_AW   220672            // 100*4 = 400
#define SMEM_BYTES 221072

// ---- static device scratch ----
__device__ __align__(16) float         g_xk[(size_t)B_TOT * 400];  // permuted col=4u+g, fp32
__device__ __align__(16) __nv_bfloat16 g_Rimg[NPADN * KEL];        // B image [n=104g+u][k]

// j-tile assignment per n-group (13 j-tiles over 8 groups; ng0 lightest: warps 0,1 also run IDM)
__device__ __constant__ int JBASE[8] = {0, 1, 3, 5, 7, 9, 11, 12};
__device__ __constant__ int JCNT[8]  = {1, 2, 2, 2, 2, 2, 1, 1};

// ============================ helpers ============================
__device__ __forceinline__ unsigned smem_u32(const void* p) {
    unsigned a;
    asm("{ .reg .u64 t; cvta.to.shared.u64 t, %1; cvt.u32.u64 %0, t; }" : "=r"(a) : "l"(p));
    return a;
}
__device__ __forceinline__ float fast_ex2(float x){ float y; asm("ex2.approx.f32 %0,%1;" : "=f"(y) : "f"(x)); return y; }
__device__ __forceinline__ float fast_rcp(float x){ float y; asm("rcp.approx.f32 %0,%1;" : "=f"(y) : "f"(x)); return y; }
__device__ __forceinline__ float fsigm(float x){ return fast_rcp(1.f + fast_ex2(-1.4426950408889634f * x)); }
__device__ __forceinline__ float htanh(float x){ float y; asm("tanh.approx.f32 %0,%1;" : "=f"(y) : "f"(x)); return y; }
__device__ __forceinline__ float tsigm(float x){ return fmaf(0.5f, htanh(0.5f * x), 0.5f); }

__device__ __forceinline__ void ldsm_x4(unsigned* r, unsigned addr) {
    asm volatile("ldmatrix.sync.aligned.m8n8.x4.shared.b16 {%0,%1,%2,%3}, [%4];"
        : "=r"(r[0]), "=r"(r[1]), "=r"(r[2]), "=r"(r[3]) : "r"(addr));
}
__device__ __forceinline__ void ldsm_x2(unsigned& r0, unsigned& r1, unsigned addr) {
    asm volatile("ldmatrix.sync.aligned.m8n8.x2.shared.b16 {%0,%1}, [%2];"
        : "=r"(r0), "=r"(r1) : "r"(addr));
}
__device__ __forceinline__ void ldsm_x1(unsigned& r0, unsigned addr) {
    asm volatile("ldmatrix.sync.aligned.m8n8.x1.shared.b16 {%0}, [%1];"
        : "=r"(r0) : "r"(addr));
}
__device__ __forceinline__ void mma16(float* c, const unsigned* a, unsigned b0, unsigned b1) {
    asm volatile("mma.sync.aligned.m16n8k16.row.col.f32.bf16.bf16.f32 "
        "{%0,%1,%2,%3}, {%4,%5,%6,%7}, {%8,%9}, {%0,%1,%2,%3};"
        : "+f"(c[0]), "+f"(c[1]), "+f"(c[2]), "+f"(c[3])
        : "r"(a[0]), "r"(a[1]), "r"(a[2]), "r"(a[3]), "r"(b0), "r"(b1));
}
__device__ __forceinline__ void mma8(float* c, unsigned a0, unsigned a1, unsigned b0) {
    asm volatile("mma.sync.aligned.m16n8k8.row.col.f32.bf16.bf16.f32 "
        "{%0,%1,%2,%3}, {%4,%5}, {%6}, {%0,%1,%2,%3};"
        : "+f"(c[0]), "+f"(c[1]), "+f"(c[2]), "+f"(c[3])
        : "r"(a0), "r"(a1), "r"(b0));
}

// ============================ setup: B image + proj + xk(fp32) ============================
__global__ void __launch_bounds__(256) setup_kernel(
    const float* __restrict__ z, const float* __restrict__ W1, const float* __restrict__ b1,
    const float* __restrict__ W2, const float* __restrict__ b2,
    const float* __restrict__ lstm_k, const float* __restrict__ lstm_r,
    const float* __restrict__ lstm_b)
{
    if (blockIdx.x >= 1024) {
        int i = (blockIdx.x - 1024) * 256 + threadIdx.x;
        if (i < NPADN * KEL) {
            int n = i / KEL, k = i % KEL;
            int g = n / 104, u = n % 104;
            float v = 0.f;
            if (u < 100) {
                int col = u + 100 * g;
                if (k < 100)      v = lstm_r[(size_t)k * 400 + col];
                else if (k < 102) v = lstm_k[(size_t)(50 + (k - 100)) * 400 + col];
            }
            g_Rimg[i] = __float2bfloat16_rn(v);
        }
        return;
    }
    const int warp = threadIdx.x >> 5, lane = threadIdx.x & 31;
    for (int b = blockIdx.x * 8 + warp; b < B_TOT; b += 8192) {
        float zr[4];
        #pragma unroll
        for (int q = 0; q < 4; q++) zr[q] = z[(size_t)b * 128 + q * 32 + lane];

        float a0 = b1[lane];
        float a1 = (lane < 18) ? b1[32 + lane] : 0.f;
        for (int i = 0; i < 128; i++) {
            float zi = __shfl_sync(0xffffffffu, zr[i >> 5], i & 31);
            a0 = fmaf(zi, W1[i * 50 + lane], a0);
            if (lane < 18) a1 = fmaf(zi, W1[i * 50 + 32 + lane], a1);
        }
        float p10 = fmaxf(a0, 0.f), p11 = fmaxf(a1, 0.f);

        float c0 = b2[lane];
        float c1 = (lane < 18) ? b2[32 + lane] : 0.f;
        for (int i = 0; i < 50; i++) {
            float pi = __shfl_sync(0xffffffffu, (i < 32) ? p10 : p11, i & 31);
            c0 = fmaf(pi, W2[i * 50 + lane], c0);
            if (lane < 18) c1 = fmaf(pi, W2[i * 50 + 32 + lane], c1);
        }
        float p20 = fmaxf(c0, 0.f), p21 = fmaxf(c1, 0.f);

        float acc[13];
        #pragma unroll
        for (int q = 0; q < 13; q++) { int j = lane + 32 * q; acc[q] = (j < 400) ? lstm_b[j] : 0.f; }
        for (int i = 0; i < 50; i++) {
            float pi = __shfl_sync(0xffffffffu, (i < 32) ? p20 : p21, i & 31);
            const float* kr = lstm_k + (size_t)i * 400;
            #pragma unroll
            for (int q = 0; q < 13; q++) { int j = lane + 32 * q; if (j < 400) acc[q] = fmaf(pi, kr[j], acc[q]); }
        }
        float* xo = g_xk + (size_t)b * 400;
        #pragma unroll
        for (int q = 0; q < 13; q++) {
            int j = lane + 32 * q;
            if (j < 400) xo[4 * (j % 100) + (j / 100)] = acc[q];
        }
    }
}

// ============================ rollout ============================
__global__ void __launch_bounds__(NTHR, 1) rollout_kernel(
    const float* __restrict__ idm_params, const float* __restrict__ idm_s,
    const float* __restrict__ sdv_acts,   const float* __restrict__ att_w,
    const float* __restrict__ att_b,      float* __restrict__ out)
{
    extern __shared__ char sm[];
    const unsigned sbase = smem_u32(sm);
    float* xk_f  = (float*)(sm + OFF_XK);
    float* att_f = (float*)(sm + OFF_ATT);
    float* aw_f  = (float*)(sm + OFF_AW);

    const int tid = threadIdx.x, lane = tid & 31, wid = tid >> 5;
    const int b0 = blockIdx.x * MCH;

    // ---- init: R image, zero A bufs, xk fp32, aw ----
    {
        const uint4* src = (const uint4*)g_Rimg;
        uint4* dR = (uint4*)(sm + OFF_R);
        for (int i = tid; i < 86528 / 16; i += NTHR) dR[i] = src[i];
        uint4 zz = make_uint4(0, 0, 0, 0);
        uint4* dA = (uint4*)(sm + OFF_A0);
        for (int i = tid; i < 26624 / 16; i += NTHR) dA[i] = zz;
        for (int i = tid; i < 100; i += NTHR) aw_f[i] = att_w[i];
        for (int idx = tid; idx < 64 * 400; idx += NTHR) {
            int row = idx / 400, jj = idx % 400;
            xk_f[row * XKW + jj] = g_xk[(size_t)(b0 + row) * 400 + jj];
        }
    }
    __syncthreads();
    if (tid < MCH) {   // sdv(0) into A0 at k=100,101
        const float2 sd = *(const float2*)(sdv_acts + (size_t)(b0 + tid) * TST * 2);
        __nv_bfloat162 pk = __floats2bfloat162_rn(sd.x, sd.y);
        *(unsigned*)(sm + OFF_A0 + tid * ROWB + 200) = *(unsigned*)&pk;
    }

    // ---- roles: 16 warps; mg = wid&1, ng = wid>>1 ----
    const int mg = wid & 1, ng = wid >> 1;
    const int jbase = JBASE[ng], jcnt = JCNT[ng];
    const int rbase = 32 * mg;
    const int amat = lane >> 3;
    const int cg = lane >> 2, ct = lane & 3;
    const int bnr = lane & 7, bq = lane >> 3;

    float c_st[2][2][4];
    #pragma unroll
    for (int a = 0; a < 2; a++)
        #pragma unroll
        for (int b = 0; b < 2; b++)
            #pragma unroll
            for (int c = 0; c < 4; c++) c_st[a][b][c] = 0.f;

    float ego_v = 0.f, ego_x = 0.f;
    if (tid < MCH) {
        const float* s0p = idm_s + (size_t)(b0 + tid) * TST * 12;
        ego_v = s0p[0]; ego_x = s0p[3];
    }
    __syncthreads();

    for (int t = 0; t < TST; t++) {
        const unsigned acur = (t & 1) ? OFF_A1 : OFF_A0;
        const unsigned anxt = (t & 1) ? OFF_A0 : OFF_A1;
        float* atb = att_f + (t & 1) * 512;

        // stage sdv(t+1) into anxt NOW (its last reads ended before sync(t-1))
        if (tid < MCH && t + 1 < TST) {
            const float2 sd = *(const float2*)(sdv_acts + ((size_t)(b0 + tid) * TST + t + 1) * 2);
            __nv_bfloat162 pk = __floats2bfloat162_rn(sd.x, sd.y);
            *(unsigned*)(sm + anxt + tid * ROWB + 200) = *(unsigned*)&pk;
        }

        float attp[2][2] = {{0.f, 0.f}, {0.f, 0.f}};

        #pragma unroll
        for (int mt = 0; mt < 2; mt++) {
            // ---- A fragments for this 16-row m-tile ----
            unsigned afr[6][4], a80, a81;
            {
                const int arow = rbase + 16 * mt + (lane & 7) + ((amat & 1) << 3);
                const int akoff = amat >> 1;
                #pragma unroll
                for (int s = 0; s < 6; s++)
                    ldsm_x4(afr[s], sbase + acur + (unsigned)arow * ROWB + (unsigned)((2 * s + akoff) << 4));
                const int a8r = rbase + 16 * mt + (lane & 7) + (((lane >> 3) & 1) << 3);
                ldsm_x2(a80, a81, sbase + acur + (unsigned)a8r * ROWB + 192u);
            }

            #pragma unroll
            for (int jl = 0; jl < 2; jl++) {
                if (jl < jcnt) {
                    const int j = jbase + jl;
                    unsigned baddr[4];
                    #pragma unroll
                    for (int g = 0; g < 4; g++)
                        baddr[g] = sbase + OFF_R + (unsigned)(104 * g + 8 * j + bnr) * ROWB;

                    float C[4][4];
                    #pragma unroll
                    for (int g = 0; g < 4; g++)
                        #pragma unroll
                        for (int q = 0; q < 4; q++) C[g][q] = 0.f;

                    // g-interleaved MMA: 4 independent accumulation chains
                    #pragma unroll
                    for (int s2 = 0; s2 < 3; s2++) {
                        unsigned b4[4][4];
                        #pragma unroll
                        for (int g = 0; g < 4; g++)
                            ldsm_x4(b4[g], baddr[g] + (unsigned)((4 * s2 + bq) << 4));
                        #pragma unroll
                        for (int g = 0; g < 4; g++)
                            mma16(C[g], afr[2 * s2], b4[g][0], b4[g][1]);
                        #pragma unroll
                        for (int g = 0; g < 4; g++)
                            mma16(C[g], afr[2 * s2 + 1], b4[g][2], b4[g][3]);
                    }
                    #pragma unroll
                    for (int g = 0; g < 4; g++) {
                        unsigned bb;
                        ldsm_x1(bb, baddr[g] + 192u);
                        mma8(C[g], a80, a81, bb);
                    }

                    // ---- epilogue: gates in-thread; xk from SMEM; c in regs ----
                    const int u0 = 8 * j + 2 * ct;
                    if (u0 < 100) {
                        const float aw0 = aw_f[u0], aw1 = aw_f[u0 + 1];
                        #pragma unroll
                        for (int ph = 0; ph < 2; ph++) {
                            const int row = rbase + 16 * mt + cg + 8 * ph;
                            const float* xr = xk_f + row * XKW + 4 * u0;
                            const float4 xv0 = *(const float4*)(xr);
                            const float4 xv1 = *(const float4*)(xr + 4);
                            float z0 = C[0][2 * ph] + xv0.x;
                            float z1 = C[1][2 * ph] + xv0.y;
                            float z2 = C[2][2 * ph] + xv0.z;
                            float z3 = C[3][2 * ph] + xv0.w;
                            float cn0 = fsigm(z1) * c_st[mt][jl][2 * ph] + tsigm(z0) * htanh(z2);
                            c_st[mt][jl][2 * ph] = cn0;
                            float h0 = htanh(cn0) * tsigm(z3);

                            float y0 = C[0][2 * ph + 1] + xv1.x;
                            float y1 = C[1][2 * ph + 1] + xv1.y;
                            float y2 = C[2][2 * ph + 1] + xv1.z;
                            float y3 = C[3][2 * ph + 1] + xv1.w;
                            float cn1 = fsigm(y1) * c_st[mt][jl][2 * ph + 1] + tsigm(y0) * htanh(y2);
                            c_st[mt][jl][2 * ph + 1] = cn1;
                            float h1 = htanh(cn1) * tsigm(y3);

                            attp[mt][ph] = fmaf(h0, aw0, fmaf(h1, aw1, attp[mt][ph]));
                            __nv_bfloat162 pk = __floats2bfloat162_rn(h0, h1);
                            *(unsigned*)(sm + anxt + row * ROWB + u0 * 2) = *(unsigned*)&pk;
                        }
                    }
                }
            }
        }

        // ---- att partial reduce over ct, write to this step's buffer ----
        #pragma unroll
        for (int mt = 0; mt < 2; mt++)
            #pragma unroll
            for (int ph = 0; ph < 2; ph++) {
                float v = attp[mt][ph];
                v += __shfl_xor_sync(0xffffffffu, v, 1);
                v += __shfl_xor_sync(0xffffffffu, v, 2);
                if (ct == 0) atb[ng * 64 + rbase + 16 * mt + cg + 8 * ph] = v;
            }
        __syncthreads();   // the ONLY barrier per step

        // ---- IDM + integrate + store (threads 0..63); others proceed to t+1 ----
        if (tid < MCH) {
            const int b = b0 + tid;
            const float* pp = idm_params + b * 5;
            const float vdes = pp[0], tgap = pp[1], jamx = pp[2], amax = pp[3];
            const float gden = 2.f * sqrtf(amax * pp[4]);
            const float* srow = idm_s + ((size_t)b * TST + t) * 12;
            float fv = srow[1], mv = srow[2], fx = srow[4], mx = srow[5];
            float fex = srow[10], mex = srow[11];

            float s = 0.f;
            #pragma unroll
            for (int q = 0; q < 8; q++) s += atb[q * 64 + tid];
            float att = fsigm(s + att_b[0]);
            att = (fex * att + (1.f - fex)) * mex;

            float v = ego_v, x = ego_x;
            float dx1 = fminf(fmaxf(fx - x, 0.1f), 1000.f);
            float gap1 = tgap * v + v * (v - fv) / gden;
            float dg1 = jamx + fmaxf(gap1, 0.f);
            float r1 = v / vdes; float r1s = r1 * r1;
            float r2 = dg1 / dx1;
            float ef = amax * (1.f - r1s * r1s - r2 * r2);
            ef = fminf(fmaxf(ef, -100000.f), 100000.f);

            float dx2 = fminf(fmaxf(mx - x, 0.1f), 1000.f);
            float gap2 = tgap * v + v * (v - mv) / gden;
            float dg2 = jamx + fmaxf(gap2, 0.f);
            float r3 = dg2 / dx2;
            float em2 = amax * (1.f - r1s * r1s - r3 * r3);
            em2 = fminf(fmaxf(em2, -100000.f), 100000.f);

            float act = (1.f - att) * ef + att * em2;
            float vn = v + act * DT;
            ego_x = x + vn * DT + 0.5f * act * DT * DT;
            ego_v = vn;

            out[(size_t)b * TST + t] = act;
            out[(size_t)B_TOT * TST + (size_t)b * TST + t] = att;
        }
    }
}

// ============================ launch ============================
extern "C" void kernel_launch(void* const* d_in, const int* in_sizes, int n_in,
                              void* d_out, int out_size) {
    const float* sampled_z  = (const float*)d_in[0];
    const float* idm_params = (const float*)d_in[1];
    const float* idm_s      = (const float*)d_in[2];
    const float* sdv_acts   = (const float*)d_in[3];
    const float* W1         = (const float*)d_in[4];
    const float* b1         = (const float*)d_in[5];
    const float* W2         = (const float*)d_in[6];
    const float* b2         = (const float*)d_in[7];
    const float* lstm_k     = (const float*)d_in[8];
    const float* lstm_r     = (const float*)d_in[9];
    const float* lstm_b     = (const float*)d_in[10];
    const float* att_w      = (const float*)d_in[11];
    const float* att_b      = (const float*)d_in[12];
    float* out = (float*)d_out;

    cudaFuncSetAttribute(rollout_kernel, cudaFuncAttributeMaxDynamicSharedMemorySize, SMEM_BYTES);

    setup_kernel<<<1024 + (NPADN * KEL + 255) / 256, 256>>>(
        sampled_z, W1, b1, W2, b2, lstm_k, lstm_r, lstm_b);
    rollout_kernel<<<B_TOT / MCH, NTHR, SMEM_BYTES>>>(idm_params, idm_s, sdv_acts, att_w, att_b, out);
}

// round 14
// speedup vs baseline: 1.5227x; 1.0221x over previous
#include <cuda_runtime.h>
#include <cuda_bf16.h>

#define B_TOT   65536
#define TST     40
#define DT      0.1f
#define MCH     64        // batch rows per CTA
#define NTHR    416       // 13 warps: warp w owns j-tile w (units 8w..8w+7), all 64 rows
#define NPADN   416       // 4 gate blocks x 104 padded units
#define KEL     104       // padded K elems (102 real), 13 chunks of 16B
#define ROWB    208       // operand-image row stride (odd chunk count -> ldsm conflict-free)
#define XKW     404       // xk smem row stride in floats (1616 B)

// ---- SMEM byte offsets (1 CTA/SM, ~218.4 KB) ----
#define OFF_R    0                 // 416*208 = 86528
#define OFF_A0   86528             // 64*208  = 13312
#define OFF_A1   99840             // 13312
#define OFF_XK   113152            // 64*1616 = 103424
#define OFF_ATT  216576            // 2 buf * 13*64*4 = 6656
#define OFF_AW   223232            // 100*4 = 400
#define SMEM_BYTES 223632

// ---- static device scratch ----
__device__ __align__(16) float         g_xk[(size_t)B_TOT * 400];  // permuted col=4u+g, fp32
__device__ __align__(16) __nv_bfloat16 g_Rimg[NPADN * KEL];        // B image [n=104g+u][k]

// ============================ helpers ============================
__device__ __forceinline__ unsigned smem_u32(const void* p) {
    unsigned a;
    asm("{ .reg .u64 t; cvta.to.shared.u64 t, %1; cvt.u32.u64 %0, t; }" : "=r"(a) : "l"(p));
    return a;
}
__device__ __forceinline__ float fast_ex2(float x){ float y; asm("ex2.approx.f32 %0,%1;" : "=f"(y) : "f"(x)); return y; }
__device__ __forceinline__ float fast_rcp(float x){ float y; asm("rcp.approx.f32 %0,%1;" : "=f"(y) : "f"(x)); return y; }
__device__ __forceinline__ float fsigm(float x){ return fast_rcp(1.f + fast_ex2(-1.4426950408889634f * x)); }
__device__ __forceinline__ float htanh(float x){ float y; asm("tanh.approx.f32 %0,%1;" : "=f"(y) : "f"(x)); return y; }
__device__ __forceinline__ float tsigm(float x){ return fmaf(0.5f, htanh(0.5f * x), 0.5f); }

__device__ __forceinline__ void ldsm_x4(unsigned* r, unsigned addr) {
    asm volatile("ldmatrix.sync.aligned.m8n8.x4.shared.b16 {%0,%1,%2,%3}, [%4];"
        : "=r"(r[0]), "=r"(r[1]), "=r"(r[2]), "=r"(r[3]) : "r"(addr));
}
__device__ __forceinline__ void ldsm_x2(unsigned& r0, unsigned& r1, unsigned addr) {
    asm volatile("ldmatrix.sync.aligned.m8n8.x2.shared.b16 {%0,%1}, [%2];"
        : "=r"(r0), "=r"(r1) : "r"(addr));
}
__device__ __forceinline__ void ldsm_x1(unsigned& r0, unsigned addr) {
    asm volatile("ldmatrix.sync.aligned.m8n8.x1.shared.b16 {%0}, [%1];"
        : "=r"(r0) : "r"(addr));
}
__device__ __forceinline__ void mma16(float* c, const unsigned* a, unsigned b0, unsigned b1) {
    asm volatile("mma.sync.aligned.m16n8k16.row.col.f32.bf16.bf16.f32 "
        "{%0,%1,%2,%3}, {%4,%5,%6,%7}, {%8,%9}, {%0,%1,%2,%3};"
        : "+f"(c[0]), "+f"(c[1]), "+f"(c[2]), "+f"(c[3])
        : "r"(a[0]), "r"(a[1]), "r"(a[2]), "r"(a[3]), "r"(b0), "r"(b1));
}
__device__ __forceinline__ void mma8(float* c, unsigned a0, unsigned a1, unsigned b0) {
    asm volatile("mma.sync.aligned.m16n8k8.row.col.f32.bf16.bf16.f32 "
        "{%0,%1,%2,%3}, {%4,%5}, {%6}, {%0,%1,%2,%3};"
        : "+f"(c[0]), "+f"(c[1]), "+f"(c[2]), "+f"(c[3])
        : "r"(a0), "r"(a1), "r"(b0));
}

// ============================ setup: B image + proj + xk(fp32) ============================
__global__ void __launch_bounds__(256) setup_kernel(
    const float* __restrict__ z, const float* __restrict__ W1, const float* __restrict__ b1,
    const float* __restrict__ W2, const float* __restrict__ b2,
    const float* __restrict__ lstm_k, const float* __restrict__ lstm_r,
    const float* __restrict__ lstm_b)
{
    if (blockIdx.x >= 1024) {
        int i = (blockIdx.x - 1024) * 256 + threadIdx.x;
        if (i < NPADN * KEL) {
            int n = i / KEL, k = i % KEL;
            int g = n / 104, u = n % 104;
            float v = 0.f;
            if (u < 100) {
                int col = u + 100 * g;
                if (k < 100)      v = lstm_r[(size_t)k * 400 + col];
                else if (k < 102) v = lstm_k[(size_t)(50 + (k - 100)) * 400 + col];
            }
            g_Rimg[i] = __float2bfloat16_rn(v);
        }
        return;
    }
    const int warp = threadIdx.x >> 5, lane = threadIdx.x & 31;
    for (int b = blockIdx.x * 8 + warp; b < B_TOT; b += 8192) {
        float zr[4];
        #pragma unroll
        for (int q = 0; q < 4; q++) zr[q] = z[(size_t)b * 128 + q * 32 + lane];

        float a0 = b1[lane];
        float a1 = (lane < 18) ? b1[32 + lane] : 0.f;
        for (int i = 0; i < 128; i++) {
            float zi = __shfl_sync(0xffffffffu, zr[i >> 5], i & 31);
            a0 = fmaf(zi, W1[i * 50 + lane], a0);
            if (lane < 18) a1 = fmaf(zi, W1[i * 50 + 32 + lane], a1);
        }
        float p10 = fmaxf(a0, 0.f), p11 = fmaxf(a1, 0.f);

        float c0 = b2[lane];
        float c1 = (lane < 18) ? b2[32 + lane] : 0.f;
        for (int i = 0; i < 50; i++) {
            float pi = __shfl_sync(0xffffffffu, (i < 32) ? p10 : p11, i & 31);
            c0 = fmaf(pi, W2[i * 50 + lane], c0);
            if (lane < 18) c1 = fmaf(pi, W2[i * 50 + 32 + lane], c1);
        }
        float p20 = fmaxf(c0, 0.f), p21 = fmaxf(c1, 0.f);

        float acc[13];
        #pragma unroll
        for (int q = 0; q < 13; q++) { int j = lane + 32 * q; acc[q] = (j < 400) ? lstm_b[j] : 0.f; }
        for (int i = 0; i < 50; i++) {
            float pi = __shfl_sync(0xffffffffu, (i < 32) ? p20 : p21, i & 31);
            const float* kr = lstm_k + (size_t)i * 400;
            #pragma unroll
            for (int q = 0; q < 13; q++) { int j = lane + 32 * q; if (j < 400) acc[q] = fmaf(pi, kr[j], acc[q]); }
        }
        float* xo = g_xk + (size_t)b * 400;
        #pragma unroll
        for (int q = 0; q < 13; q++) {
            int j = lane + 32 * q;
            if (j < 400) xo[4 * (j % 100) + (j / 100)] = acc[q];
        }
    }
}

// ============================ rollout ============================
__global__ void __launch_bounds__(NTHR, 1) rollout_kernel(
    const float* __restrict__ idm_params, const float* __restrict__ idm_s,
    const float* __restrict__ sdv_acts,   const float* __restrict__ att_w,
    const float* __restrict__ att_b,      float* __restrict__ out)
{
    extern __shared__ char sm[];
    const unsigned sbase = smem_u32(sm);
    float* xk_f  = (float*)(sm + OFF_XK);
    float* att_f = (float*)(sm + OFF_ATT);
    float* aw_f  = (float*)(sm + OFF_AW);

    const int tid = threadIdx.x, lane = tid & 31, wid = tid >> 5;
    const int b0 = blockIdx.x * MCH;

    // ---- init: R image, zero A bufs, xk fp32, aw ----
    {
        const uint4* src = (const uint4*)g_Rimg;
        uint4* dR = (uint4*)(sm + OFF_R);
        for (int i = tid; i < 86528 / 16; i += NTHR) dR[i] = src[i];
        uint4 zz = make_uint4(0, 0, 0, 0);
        uint4* dA = (uint4*)(sm + OFF_A0);
        for (int i = tid; i < 26624 / 16; i += NTHR) dA[i] = zz;
        for (int i = tid; i < 100; i += NTHR) aw_f[i] = att_w[i];
        for (int idx = tid; idx < 64 * 400; idx += NTHR) {
            int row = idx / 400, jj = idx % 400;
            xk_f[row * XKW + jj] = g_xk[(size_t)(b0 + row) * 400 + jj];
        }
    }
    __syncthreads();
    if (tid < MCH) {   // sdv(0) into A0 at k=100,101
        const float2 sd = *(const float2*)(sdv_acts + (size_t)(b0 + tid) * TST * 2);
        __nv_bfloat162 pk = __floats2bfloat162_rn(sd.x, sd.y);
        *(unsigned*)(sm + OFF_A0 + tid * ROWB + 200) = *(unsigned*)&pk;
    }

    // ---- roles: 13 warps; warp wid owns j-tile j = wid, all 4 m-tiles ----
    const int j = wid;
    const int amat = lane >> 3;
    const int cg = lane >> 2, ct = lane & 3;
    const int bnr = lane & 7, bq = lane >> 3;

    // ---- B fragments: loaded ONCE, live in registers for all 40 steps ----
    unsigned bB[4][13];
    #pragma unroll
    for (int g = 0; g < 4; g++) {
        const unsigned baddr = sbase + OFF_R + (unsigned)(104 * g + 8 * j + bnr) * ROWB;
        ldsm_x4(&bB[g][0], baddr + ((0 + bq) << 4));
        ldsm_x4(&bB[g][4], baddr + ((4 + bq) << 4));
        ldsm_x4(&bB[g][8], baddr + ((8 + bq) << 4));
        ldsm_x1(bB[g][12], baddr + 192u);
    }

    float c_st[4][4];   // [mt][2ph+unit]
    #pragma unroll
    for (int a = 0; a < 4; a++)
        #pragma unroll
        for (int b = 0; b < 4; b++) c_st[a][b] = 0.f;

    float ego_v = 0.f, ego_x = 0.f;
    if (tid < MCH) {
        const float* s0p = idm_s + (size_t)(b0 + tid) * TST * 12;
        ego_v = s0p[0]; ego_x = s0p[3];
    }
    __syncthreads();

    const int u0 = 8 * j + 2 * ct;
    const float aw0 = (u0 < 100) ? aw_f[u0] : 0.f;
    const float aw1 = (u0 < 100) ? aw_f[u0 + 1] : 0.f;

    for (int t = 0; t < TST; t++) {
        const unsigned acur = (t & 1) ? OFF_A1 : OFF_A0;
        const unsigned anxt = (t & 1) ? OFF_A0 : OFF_A1;
        float* atb = att_f + (t & 1) * (13 * 64);

        // stage sdv(t+1) into anxt NOW (its last reads ended before sync(t-1))
        if (tid < MCH && t + 1 < TST) {
            const float2 sd = *(const float2*)(sdv_acts + ((size_t)(b0 + tid) * TST + t + 1) * 2);
            __nv_bfloat162 pk = __floats2bfloat162_rn(sd.x, sd.y);
            *(unsigned*)(sm + anxt + tid * ROWB + 200) = *(unsigned*)&pk;
        }

        float attp[4][2];
        #pragma unroll
        for (int mt = 0; mt < 4; mt++) { attp[mt][0] = 0.f; attp[mt][1] = 0.f; }

        #pragma unroll
        for (int mt = 0; mt < 4; mt++) {
            // ---- A fragments for this 16-row m-tile ----
            unsigned afr[6][4], a80, a81;
            {
                const int arow = 16 * mt + (lane & 7) + ((amat & 1) << 3);
                const int akoff = amat >> 1;
                #pragma unroll
                for (int s = 0; s < 6; s++)
                    ldsm_x4(afr[s], sbase + acur + (unsigned)arow * ROWB + (unsigned)((2 * s + akoff) << 4));
                const int a8r = 16 * mt + (lane & 7) + (((lane >> 3) & 1) << 3);
                ldsm_x2(a80, a81, sbase + acur + (unsigned)a8r * ROWB + 192u);
            }

            float C[4][4];
            #pragma unroll
            for (int g = 0; g < 4; g++)
                #pragma unroll
                for (int q = 0; q < 4; q++) C[g][q] = 0.f;

            // g-interleaved MMA: 4 independent chains, B from registers
            #pragma unroll
            for (int s2 = 0; s2 < 3; s2++) {
                #pragma unroll
                for (int g = 0; g < 4; g++)
                    mma16(C[g], afr[2 * s2], bB[g][4 * s2], bB[g][4 * s2 + 1]);
                #pragma unroll
                for (int g = 0; g < 4; g++)
                    mma16(C[g], afr[2 * s2 + 1], bB[g][4 * s2 + 2], bB[g][4 * s2 + 3]);
            }
            #pragma unroll
            for (int g = 0; g < 4; g++)
                mma8(C[g], a80, a81, bB[g][12]);

            // ---- epilogue: gates in-thread; xk from SMEM; c in regs ----
            if (u0 < 100) {
                #pragma unroll
                for (int ph = 0; ph < 2; ph++) {
                    const int row = 16 * mt + cg + 8 * ph;
                    const float* xr = xk_f + row * XKW + 4 * u0;
                    const float4 xv0 = *(const float4*)(xr);
                    const float4 xv1 = *(const float4*)(xr + 4);
                    float z0 = C[0][2 * ph] + xv0.x;
                    float z1 = C[1][2 * ph] + xv0.y;
                    float z2 = C[2][2 * ph] + xv0.z;
                    float z3 = C[3][2 * ph] + xv0.w;
                    float cn0 = fsigm(z1) * c_st[mt][2 * ph] + tsigm(z0) * htanh(z2);
                    c_st[mt][2 * ph] = cn0;
                    float h0 = htanh(cn0) * tsigm(z3);

                    float y0 = C[0][2 * ph + 1] + xv1.x;
                    float y1 = C[1][2 * ph + 1] + xv1.y;
                    float y2 = C[2][2 * ph + 1] + xv1.z;
                    float y3 = C[3][2 * ph + 1] + xv1.w;
                    float cn1 = fsigm(y1) * c_st[mt][2 * ph + 1] + tsigm(y0) * htanh(y2);
                    c_st[mt][2 * ph + 1] = cn1;
                    float h1 = htanh(cn1) * tsigm(y3);

                    attp[mt][ph] = fmaf(h0, aw0, fmaf(h1, aw1, attp[mt][ph]));
                    __nv_bfloat162 pk = __floats2bfloat162_rn(h0, h1);
                    *(unsigned*)(sm + anxt + row * ROWB + u0 * 2) = *(unsigned*)&pk;
                }
            }
        }

        // ---- att partial reduce over ct, write to this step's buffer ----
        #pragma unroll
        for (int mt = 0; mt < 4; mt++)
            #pragma unroll
            for (int ph = 0; ph < 2; ph++) {
                float v = attp[mt][ph];
                v += __shfl_xor_sync(0xffffffffu, v, 1);
                v += __shfl_xor_sync(0xffffffffu, v, 2);
                if (ct == 0) atb[j * 64 + 16 * mt + cg + 8 * ph] = v;
            }
        __syncthreads();   // the ONLY barrier per step

        // ---- IDM + integrate + store (threads 0..63); others proceed to t+1 ----
        if (tid < MCH) {
            const int b = b0 + tid;
            const float* pp = idm_params + b * 5;
            const float vdes = pp[0], tgap = pp[1], jamx = pp[2], amax = pp[3];
            const float gden = 2.f * sqrtf(amax * pp[4]);
            const float* srow = idm_s + ((size_t)b * TST + t) * 12;
            float fv = srow[1], mv = srow[2], fx = srow[4], mx = srow[5];
            float fex = srow[10], mex = srow[11];

            float s = 0.f;
            #pragma unroll
            for (int q = 0; q < 13; q++) s += atb[q * 64 + tid];
            float att = fsigm(s + att_b[0]);
            att = (fex * att + (1.f - fex)) * mex;

            float v = ego_v, x = ego_x;
            float dx1 = fminf(fmaxf(fx - x, 0.1f), 1000.f);
            float gap1 = tgap * v + v * (v - fv) / gden;
            float dg1 = jamx + fmaxf(gap1, 0.f);
            float r1 = v / vdes; float r1s = r1 * r1;
            float r2 = dg1 / dx1;
            float ef = amax * (1.f - r1s * r1s - r2 * r2);
            ef = fminf(fmaxf(ef, -100000.f), 100000.f);

            float dx2 = fminf(fmaxf(mx - x, 0.1f), 1000.f);
            float gap2 = tgap * v + v * (v - mv) / gden;
            float dg2 = jamx + fmaxf(gap2, 0.f);
            float r3 = dg2 / dx2;
            float em2 = amax * (1.f - r1s * r1s - r3 * r3);
            em2 = fminf(fmaxf(em2, -100000.f), 100000.f);

            float act = (1.f - att) * ef + att * em2;
            float vn = v + act * DT;
            ego_x = x + vn * DT + 0.5f * act * DT * DT;
            ego_v = vn;

            out[(size_t)b * TST + t] = act;
            out[(size_t)B_TOT * TST + (size_t)b * TST + t] = att;
        }
    }
}

// ============================ launch ============================
extern "C" void kernel_launch(void* const* d_in, const int* in_sizes, int n_in,
                              void* d_out, int out_size) {
    const float* sampled_z  = (const float*)d_in[0];
    const float* idm_params = (const float*)d_in[1];
    const float* idm_s      = (const float*)d_in[2];
    const float* sdv_acts   = (const float*)d_in[3];
    const float* W1         = (const float*)d_in[4];
    const float* b1         = (const float*)d_in[5];
    const float* W2         = (const float*)d_in[6];
    const float* b2         = (const float*)d_in[7];
    const float* lstm_k     = (const float*)d_in[8];
    const float* lstm_r     = (const float*)d_in[9];
    const float* lstm_b     = (const float*)d_in[10];
    const float* att_w      = (const float*)d_in[11];
    const float* att_b      = (const float*)d_in[12];
    float* out = (float*)d_out;

    cudaFuncSetAttribute(rollout_kernel, cudaFuncAttributeMaxDynamicSharedMemorySize, SMEM_BYTES);

    setup_kernel<<<1024 + (NPADN * KEL + 255) / 256, 256>>>(
        sampled_z, W1, b1, W2, b2, lstm_k, lstm_r, lstm_b);
    rollout_kernel<<<B_TOT / MCH, NTHR, SMEM_BYTES>>>(idm_params, idm_s, sdv_acts, att_w, att_b, out);
}